// round 7
// baseline (speedup 1.0000x reference)
#include <cuda_runtime.h>
#include <cstdint>
#include <mma.h>

using namespace nvcuda;

namespace {
constexpr int B  = 2;
constexpr int S  = 2048;
constexpr int E  = 1024;
constexpr int H  = 16;
constexpr int DH = 64;
constexpr int M  = B * S;    // 4096
constexpr int BH = B * H;    // 32
constexpr long long OUT_ELEMS = (long long)B * S * E;
constexpr long long W_ELEMS   = (long long)B * H * S * S;
constexpr float ATTN_SCALE = 0.125f;

constexpr int BQ  = 128;     // q rows per tile
constexpr int BK  = 64;      // k cols per tile
constexpr int NKT = S / BK;  // 32
constexpr int LD  = 68;      // attn smem stride
constexpr int GLD = 36;      // gemm smem stride
constexpr int NTILES = (S / BQ) * BH;  // 512
constexpr int NSTG = E / 32;           // 32 gemm k-stages
}

// Scratch (__device__ globals)
__device__ float g_qh[(long long)BH * S * DH];
__device__ float g_kh[(long long)BH * S * DH];
__device__ float g_vh[(long long)BH * S * DH];
__device__ float g_att[(long long)M * E];
__device__ float g_wfallback[W_ELEMS];
__device__ float g_qr[(long long)M * E];      // pre-rounded inputs
__device__ float g_kr[(long long)M * E];
__device__ float g_vr[(long long)M * E];
__device__ float g_wr[4ll * E * E];           // pre-rounded Wq,Wk,Wv,Wo
__device__ unsigned g_work;

__device__ __forceinline__ float tf32r(float x) { return wmma::__float_to_tf32(x); }

__device__ __forceinline__ void cp_async16(unsigned dst, const float* src) {
    asm volatile("cp.async.cg.shared.global [%0], [%1], 16;\n" :: "r"(dst), "l"(src));
}
__device__ __forceinline__ void cp_commit() {
    asm volatile("cp.async.commit_group;\n" ::: "memory");
}
template <int N>
__device__ __forceinline__ void cp_wait() {
    asm volatile("cp.async.wait_group %0;\n" :: "n"(N) : "memory");
}

// ---------------------------------------------------------------------------
// Pre-round: tf32-round q,k,v and the 4 weight matrices into scratch.
// Also resets the attention work counter.
// ---------------------------------------------------------------------------
__global__ void __launch_bounds__(256)
preround_kernel(const float* __restrict__ q, const float* __restrict__ k,
                const float* __restrict__ v,
                const float* __restrict__ Wq, const float* __restrict__ Wk,
                const float* __restrict__ Wv, const float* __restrict__ Wo)
{
    if (blockIdx.x == 0 && threadIdx.x == 0) g_work = 0u;

    const long long n4_x = (long long)M * E / 4;   // 1048576 float4 per input
    const long long n4_w = (long long)E * E / 4;   // 262144 float4 per weight
    const long long total = 3 * n4_x + 4 * n4_w;

    for (long long idx = (long long)blockIdx.x * blockDim.x + threadIdx.x;
         idx < total; idx += (long long)gridDim.x * blockDim.x) {
        const float4* src; float4* dst; long long off;
        if (idx < n4_x)            { src = (const float4*)q;  dst = (float4*)g_qr; off = idx; }
        else if (idx < 2 * n4_x)   { src = (const float4*)k;  dst = (float4*)g_kr; off = idx - n4_x; }
        else if (idx < 3 * n4_x)   { src = (const float4*)v;  dst = (float4*)g_vr; off = idx - 2 * n4_x; }
        else {
            long long w = idx - 3 * n4_x;
            int wi = (int)(w / n4_w);
            off = w - (long long)wi * n4_w;
            src = (const float4*)((wi == 0) ? Wq : (wi == 1) ? Wk : (wi == 2) ? Wv : Wo);
            dst = (float4*)(g_wr + (long long)wi * E * E);
        }
        float4 t = src[off];
        t.x = tf32r(t.x); t.y = tf32r(t.y); t.z = tf32r(t.z); t.w = tf32r(t.w);
        dst[off] = t;
    }
}

// ---------------------------------------------------------------------------
// Projection GEMM, 2-stage cp.async ring (inputs pre-rounded to tf32).
// out = (A @ W^T + bias) * scale. Modes 0/1/2 scatter tf32-rounded output to
// head layout; mode 3 writes flat fp32.
// ---------------------------------------------------------------------------
struct GemmSmem {
    float A[2][128][GLD];     // 36864 B
    float Bm[2][128][GLD];    // 36864 B
    float scr[8][16 * 20];    // 10240 B
};

__global__ void __launch_bounds__(256, 2)
gemm_tf32_kernel(const float* __restrict__ bias, float scale, int mode,
                 float* __restrict__ outFlat)
{
    extern __shared__ __align__(16) char smem_raw[];
    GemmSmem* sm = (GemmSmem*)smem_raw;

    const float* Aeff = (mode == 0) ? g_qr : (mode == 1) ? g_kr
                      : (mode == 2) ? g_vr : g_att;
    const float* Wt = g_wr + (long long)mode * E * E;

    const int bm = blockIdx.y * 128;
    const int bn = blockIdx.x * 128;
    const int tid  = threadIdx.x;
    const int warp = tid >> 5;
    const int lane = tid & 31;
    const int warpM = warp >> 2;
    const int warpN = warp & 3;

    const unsigned smA = (unsigned)__cvta_generic_to_shared(&sm->A[0][0][0]);
    const unsigned smB = (unsigned)__cvta_generic_to_shared(&sm->Bm[0][0][0]);
    const unsigned bufBytes = 128 * GLD * 4;

    auto issue = [&](int s, int buf) {
        const int k0 = s * 32;
        #pragma unroll
        for (int i = tid; i < 128 * 8; i += 256) {
            const int r = i >> 3, c4 = i & 7;
            const unsigned o = (unsigned)buf * bufBytes + (unsigned)(r * GLD + c4 * 4) * 4;
            cp_async16(smA + o, Aeff + (size_t)(bm + r) * E + k0 + c4 * 4);
            cp_async16(smB + o, Wt   + (size_t)(bn + r) * E + k0 + c4 * 4);
        }
    };

    wmma::fragment<wmma::accumulator, 16, 16, 8, float> c[4][2];
    #pragma unroll
    for (int mi = 0; mi < 4; ++mi)
        #pragma unroll
        for (int ni = 0; ni < 2; ++ni)
            wmma::fill_fragment(c[mi][ni], 0.0f);

    issue(0, 0);
    cp_commit();

    for (int s = 0; s < NSTG; ++s) {
        cp_wait<0>();
        __syncthreads();
        if (s + 1 < NSTG) { issue(s + 1, (s + 1) & 1); cp_commit(); }
        const int buf = s & 1;

        #pragma unroll
        for (int kc = 0; kc < 4; ++kc) {
            wmma::fragment<wmma::matrix_a, 16, 16, 8, wmma::precision::tf32, wmma::row_major> a[4];
            wmma::fragment<wmma::matrix_b, 16, 16, 8, wmma::precision::tf32, wmma::col_major> b[2];
            #pragma unroll
            for (int mi = 0; mi < 4; ++mi)
                wmma::load_matrix_sync(a[mi], &sm->A[buf][warpM * 64 + mi * 16][kc * 8], GLD);
            #pragma unroll
            for (int ni = 0; ni < 2; ++ni)
                wmma::load_matrix_sync(b[ni], &sm->Bm[buf][warpN * 32 + ni * 16][kc * 8], GLD);
            #pragma unroll
            for (int mi = 0; mi < 4; ++mi)
                #pragma unroll
                for (int ni = 0; ni < 2; ++ni)
                    wmma::mma_sync(c[mi][ni], a[mi], b[ni], c[mi][ni]);
        }
    }

    float* outHeads = (mode == 0) ? g_qh : (mode == 1) ? g_kh : g_vh;

    #pragma unroll
    for (int mi = 0; mi < 4; ++mi) {
        #pragma unroll
        for (int ni = 0; ni < 2; ++ni) {
            wmma::store_matrix_sync(&sm->scr[warp][0], c[mi][ni], 20, wmma::mem_row_major);
            __syncwarp();
            const int m0 = bm + warpM * 64 + mi * 16;
            const int n0 = bn + warpN * 32 + ni * 16;
            #pragma unroll
            for (int it = 0; it < 8; ++it) {
                const int idx = lane + it * 32;
                const int r = idx >> 4, cc = idx & 15;
                const int m = m0 + r;
                const int n = n0 + cc;
                const float v = (sm->scr[warp][r * 20 + cc] + bias[n]) * scale;
                if (mode == 3) {
                    outFlat[(size_t)m * E + n] = v;
                } else {
                    const int b_ = m >> 11, s_ = m & (S - 1);
                    const int h_ = n >> 6,  d_ = n & 63;
                    outHeads[(((size_t)(b_ * H + h_)) * S + s_) * DH + d_] = tf32r(v);
                }
            }
            __syncwarp();
        }
    }
}

// ---------------------------------------------------------------------------
// Fused attention, one CTA-sync per k-iteration.
// Warp w owns P rows [w*16, w*16+16) for QK-store, exp, PV A-operand.
// Q lives in registers; K/V in a 2-stage cp.async ring; tiles pulled from an
// atomic work counter. p~ = exp(S) written unnormalized; fixup scales by 1/l.
// ---------------------------------------------------------------------------
struct AttnSmem {
    float K[2][BK][LD];   // 34816 B
    float V[2][BK][LD];   // 34816 B
    float P[BQ][LD];      // 34816 B
    float l[BQ];
    float invl[BQ];
};

__global__ void __launch_bounds__(256, 2)
attn_fused_kernel(float* __restrict__ outw, int use_fb)
{
    extern __shared__ __align__(16) char smem_raw[];
    AttnSmem* sm = (AttnSmem*)smem_raw;
    __shared__ unsigned s_tile;

    float* wts = use_fb ? g_wfallback : outw;

    const int tid  = threadIdx.x;
    const int warp = tid >> 5;
    const int lane = tid & 31;
    const int erow = warp * 16 + (lane >> 1);   // row this lane exps
    const int ecol = (lane & 1) * 32;           // col half

    const unsigned smK0 = (unsigned)__cvta_generic_to_shared(&sm->K[0][0][0]);
    const unsigned smK1 = (unsigned)__cvta_generic_to_shared(&sm->K[1][0][0]);
    const unsigned smV0 = (unsigned)__cvta_generic_to_shared(&sm->V[0][0][0]);
    const unsigned smV1 = (unsigned)__cvta_generic_to_shared(&sm->V[1][0][0]);

    while (true) {
        if (tid == 0) s_tile = atomicAdd(&g_work, 1u);
        __syncthreads();               // also guards smem reuse from prior tile
        const unsigned tile = s_tile;
        if (tile >= (unsigned)NTILES) break;

        const int bh = (int)(tile >> 4);        // 16 q-tiles per bh
        const int q0 = (int)(tile & 15) * BQ;
        const float* Qg = g_qh + (size_t)bh * S * DH;
        const float* Kg = g_kh + (size_t)bh * S * DH;
        const float* Vg = g_vh + (size_t)bh * S * DH;
        float* Wb = wts + (size_t)bh * S * S;

        // --- stage Q through K buffers, load into register fragments ---
        #pragma unroll
        for (int i = tid; i < BQ * 16; i += 256) {
            const int r = i >> 4, c4 = i & 15;
            const unsigned dst = (r < 64)
                ? smK0 + (unsigned)(r * LD + c4 * 4) * 4
                : smK1 + (unsigned)((r - 64) * LD + c4 * 4) * 4;
            cp_async16(dst, Qg + (size_t)(q0 + r) * DH + c4 * 4);
        }
        cp_commit();
        cp_wait<0>();
        __syncthreads();

        wmma::fragment<wmma::matrix_a, 16, 16, 8, wmma::precision::tf32, wmma::row_major> aq[8];
        {
            const float* qbase = (warp < 4) ? &sm->K[0][warp * 16][0]
                                            : &sm->K[1][(warp - 4) * 16][0];
            #pragma unroll
            for (int kc = 0; kc < 8; ++kc)
                wmma::load_matrix_sync(aq[kc], qbase + kc * 8, LD);
        }
        __syncthreads();

        // --- stage 0 of the K/V ring ---
        #pragma unroll
        for (int i = tid; i < BK * 16; i += 256) {
            const int r = i >> 4, c4 = i & 15;
            const unsigned o = (unsigned)(r * LD + c4 * 4) * 4;
            cp_async16(smK0 + o, Kg + (size_t)r * DH + c4 * 4);
            cp_async16(smV0 + o, Vg + (size_t)r * DH + c4 * 4);
        }
        cp_commit();

        wmma::fragment<wmma::accumulator, 16, 16, 8, float> o[4];
        #pragma unroll
        for (int ni = 0; ni < 4; ++ni) wmma::fill_fragment(o[ni], 0.0f);
        float l_acc = 0.0f;

        for (int t = 0; t < NKT; ++t) {
            cp_wait<0>();
            __syncthreads();
            if (t + 1 < NKT) {
                const unsigned dK = ((t + 1) & 1) ? smK1 : smK0;
                const unsigned dV = ((t + 1) & 1) ? smV1 : smV0;
                #pragma unroll
                for (int i = tid; i < BK * 16; i += 256) {
                    const int r = i >> 4, c4 = i & 15;
                    const unsigned off = (unsigned)(r * LD + c4 * 4) * 4;
                    cp_async16(dK + off, Kg + (size_t)((t + 1) * BK + r) * DH + c4 * 4);
                    cp_async16(dV + off, Vg + (size_t)((t + 1) * BK + r) * DH + c4 * 4);
                }
                cp_commit();
            }
            const int buf = t & 1;

            // QK: warp tile 16 x 64
            {
                wmma::fragment<wmma::accumulator, 16, 16, 8, float> c[4];
                #pragma unroll
                for (int ni = 0; ni < 4; ++ni) wmma::fill_fragment(c[ni], 0.0f);
                #pragma unroll
                for (int kc = 0; kc < 8; ++kc) {
                    #pragma unroll
                    for (int ni = 0; ni < 4; ++ni) {
                        wmma::fragment<wmma::matrix_b, 16, 16, 8, wmma::precision::tf32, wmma::col_major> b;
                        wmma::load_matrix_sync(b, &sm->K[buf][ni * 16][kc * 8], LD);
                        wmma::mma_sync(c[ni], aq[kc], b, c[ni]);
                    }
                }
                #pragma unroll
                for (int ni = 0; ni < 4; ++ni)
                    wmma::store_matrix_sync(&sm->P[warp * 16][ni * 16], c[ni], LD,
                                            wmma::mem_row_major);
            }
            __syncwarp();

            // exp + gmem p~ write + rowsum (warp-local rows)
            {
                float rs = 0.0f;
                float* prow = &sm->P[erow][ecol];
                float* gdst = &Wb[(size_t)(q0 + erow) * S + t * BK + ecol];
                #pragma unroll
                for (int j4 = 0; j4 < 8; ++j4) {
                    float4 x = *(float4*)&prow[j4 * 4];
                    x.x = __expf(fminf(x.x, 60.f));
                    x.y = __expf(fminf(x.y, 60.f));
                    x.z = __expf(fminf(x.z, 60.f));
                    x.w = __expf(fminf(x.w, 60.f));
                    *(float4*)&gdst[j4 * 4] = x;
                    rs += x.x + x.y + x.z + x.w;
                    x.x = tf32r(x.x); x.y = tf32r(x.y); x.z = tf32r(x.z); x.w = tf32r(x.w);
                    *(float4*)&prow[j4 * 4] = x;
                }
                rs += __shfl_xor_sync(0xffffffffu, rs, 1);
                l_acc += rs;
            }
            __syncwarp();

            // PV: o += P(16x64) @ V(64x64)
            #pragma unroll
            for (int kc = 0; kc < 8; ++kc) {
                wmma::fragment<wmma::matrix_a, 16, 16, 8, wmma::precision::tf32, wmma::row_major> a;
                wmma::load_matrix_sync(a, &sm->P[warp * 16][kc * 8], LD);
                #pragma unroll
                for (int ni = 0; ni < 4; ++ni) {
                    wmma::fragment<wmma::matrix_b, 16, 16, 8, wmma::precision::tf32, wmma::row_major> b;
                    wmma::load_matrix_sync(b, &sm->V[buf][kc * 8][ni * 16], LD);
                    wmma::mma_sync(o[ni], a, b, o[ni]);
                }
            }
        }

        // --- l, invl ---
        if ((lane & 1) == 0) sm->l[erow] = l_acc;
        __syncthreads();
        if (tid < BQ) sm->invl[tid] = 1.0f / sm->l[tid];
        __syncthreads();

        // --- fixup: scale this tile's probs strip by inv_l ---
        for (int i = tid; i < BQ * (S / 4); i += 256) {
            const int r = i >> 9, c4 = i & 511;
            const float sc = sm->invl[r];
            float* p = &Wb[(size_t)(q0 + r) * S + c4 * 4];
            float4 x = *(float4*)p;
            x.x *= sc; x.y *= sc; x.z *= sc; x.w *= sc;
            *(float4*)p = x;
        }

        // --- O: frags -> P smem -> scaled, tf32-rounded scatter to g_att ---
        #pragma unroll
        for (int ni = 0; ni < 4; ++ni)
            wmma::store_matrix_sync(&sm->P[warp * 16][ni * 16], o[ni], LD,
                                    wmma::mem_row_major);
        __syncwarp();
        {
            const int b_ = bh >> 4, h_ = bh & 15;
            const float sc = sm->invl[erow];
            float* dst = &g_att[((size_t)(b_ * S + q0 + erow)) * E + h_ * DH + ecol];
            const float* src = &sm->P[erow][ecol];
            #pragma unroll
            for (int j4 = 0; j4 < 8; ++j4) {
                float4 x = *(const float4*)&src[j4 * 4];
                x.x = tf32r(x.x * sc); x.y = tf32r(x.y * sc);
                x.z = tf32r(x.z * sc); x.w = tf32r(x.w * sc);
                *(float4*)&dst[j4 * 4] = x;
            }
        }
        // loop-top __syncthreads guards smem reuse
    }
}

// ---------------------------------------------------------------------------
extern "C" void kernel_launch(void* const* d_in, const int* in_sizes, int n_in,
                              void* d_out, int out_size)
{
    const float* q  = (const float*)d_in[0];
    const float* k  = (const float*)d_in[1];
    const float* v  = (const float*)d_in[2];
    const float* Wq = (const float*)d_in[3];
    const float* bq = (const float*)d_in[4];
    const float* Wk = (const float*)d_in[5];
    const float* bk = (const float*)d_in[6];
    const float* Wv = (const float*)d_in[7];
    const float* bv = (const float*)d_in[8];
    const float* Wo = (const float*)d_in[9];
    const float* bo = (const float*)d_in[10];
    float* out = (float*)d_out;

    const int use_fb = ((long long)out_size < OUT_ELEMS + W_ELEMS) ? 1 : 0;
    float* outw = out + OUT_ELEMS;

    static int smem_set = 0;
    const int attn_smem = (int)sizeof(AttnSmem);
    const int gemm_smem = (int)sizeof(GemmSmem);
    if (!smem_set) {
        cudaFuncSetAttribute(attn_fused_kernel,
                             cudaFuncAttributeMaxDynamicSharedMemorySize, attn_smem);
        cudaFuncSetAttribute(gemm_tf32_kernel,
                             cudaFuncAttributeMaxDynamicSharedMemorySize, gemm_smem);
        smem_set = 1;
    }

    const dim3 blk(256);
    const dim3 gemm_grid(E / 128, M / 128);   // (8, 32)

    preround_kernel<<<1024, blk>>>(q, k, v, Wq, Wk, Wv, Wo);

    gemm_tf32_kernel<<<gemm_grid, blk, gemm_smem>>>(bq, ATTN_SCALE, 0, nullptr);
    gemm_tf32_kernel<<<gemm_grid, blk, gemm_smem>>>(bk, 1.0f,       1, nullptr);
    gemm_tf32_kernel<<<gemm_grid, blk, gemm_smem>>>(bv, 1.0f,       2, nullptr);

    attn_fused_kernel<<<dim3(304), blk, attn_smem>>>(outw, use_fb);

    gemm_tf32_kernel<<<gemm_grid, blk, gemm_smem>>>(bo, 1.0f, 3, out);
}

// round 8
// speedup vs baseline: 2.7324x; 2.7324x over previous
#include <cuda_runtime.h>
#include <cstdint>
#include <cuda_fp16.h>
#include <mma.h>

using namespace nvcuda;

namespace {
constexpr int B  = 2;
constexpr int S  = 2048;
constexpr int E  = 1024;
constexpr int H  = 16;
constexpr int DH = 64;
constexpr int M  = B * S;    // 4096
constexpr int BH = B * H;    // 32
constexpr long long OUT_ELEMS = (long long)B * S * E;
constexpr long long W_ELEMS   = (long long)B * H * S * S;
constexpr float ATTN_SCALE = 0.125f;

constexpr int BQ  = 64;      // q rows per tile
constexpr int BK  = 64;      // k cols per tile
constexpr int NKT = S / BK;  // 32
constexpr int HLD = 72;      // fp16 smem stride (64 + 8)
constexpr int PLD = 68;      // fp32 P stride
constexpr int NSTG = E / 64; // 16 gemm k-stages
constexpr float EXP_OFF = 8.0f;   // logit shift (cancels in softmax)
}

// Scratch (__device__ globals)
__device__ __half g_qr[(long long)M * E];
__device__ __half g_kr[(long long)M * E];
__device__ __half g_vr[(long long)M * E];
__device__ __half g_wr[4ll * E * E];
__device__ __half g_qh[(long long)BH * S * DH];
__device__ __half g_kh[(long long)BH * S * DH];
__device__ __half g_vh[(long long)BH * S * DH];
__device__ __half g_att[(long long)M * E];
__device__ float  g_wfallback[W_ELEMS];

__device__ __forceinline__ void cp_async16(unsigned dst, const void* src) {
    asm volatile("cp.async.cg.shared.global [%0], [%1], 16;\n" :: "r"(dst), "l"(src));
}
__device__ __forceinline__ void cp_commit() {
    asm volatile("cp.async.commit_group;\n" ::: "memory");
}
template <int N>
__device__ __forceinline__ void cp_wait() {
    asm volatile("cp.async.wait_group %0;\n" :: "n"(N) : "memory");
}

// ---------------------------------------------------------------------------
// Pre-round: convert q,k,v and the 4 weight matrices to fp16 scratch.
// ---------------------------------------------------------------------------
__global__ void __launch_bounds__(256)
preround_kernel(const float* __restrict__ q, const float* __restrict__ k,
                const float* __restrict__ v,
                const float* __restrict__ Wq, const float* __restrict__ Wk,
                const float* __restrict__ Wv, const float* __restrict__ Wo)
{
    const long long n4_x = (long long)M * E / 4;
    const long long n4_w = (long long)E * E / 4;
    const long long total = 3 * n4_x + 4 * n4_w;

    for (long long idx = (long long)blockIdx.x * blockDim.x + threadIdx.x;
         idx < total; idx += (long long)gridDim.x * blockDim.x) {
        const float4* src; __half2* dst; long long off;
        if (idx < n4_x)          { src = (const float4*)q; dst = (__half2*)g_qr; off = idx; }
        else if (idx < 2 * n4_x) { src = (const float4*)k; dst = (__half2*)g_kr; off = idx - n4_x; }
        else if (idx < 3 * n4_x) { src = (const float4*)v; dst = (__half2*)g_vr; off = idx - 2 * n4_x; }
        else {
            long long w = idx - 3 * n4_x;
            int wi = (int)(w / n4_w);
            off = w - (long long)wi * n4_w;
            src = (const float4*)((wi == 0) ? Wq : (wi == 1) ? Wk : (wi == 2) ? Wv : Wo);
            dst = (__half2*)(g_wr + (long long)wi * E * E);
        }
        float4 t = src[off];
        dst[off * 2]     = __floats2half2_rn(t.x, t.y);
        dst[off * 2 + 1] = __floats2half2_rn(t.z, t.w);
    }
}

// ---------------------------------------------------------------------------
// Projection GEMM (fp16 operands, fp32 accumulate), 2-stage cp.async ring.
// out = (A @ W^T + bias) * scale. Modes 0/1/2 scatter fp16 to head layout;
// mode 3 writes flat fp32.
// ---------------------------------------------------------------------------
struct GemmSmem {
    __half A[2][128][HLD];    // 36864 B
    __half Bm[2][128][HLD];   // 36864 B
    float scr[8][16 * 20];    // 10240 B
};

__global__ void __launch_bounds__(256, 2)
gemm_fp16_kernel(const float* __restrict__ bias, float scale, int mode,
                 float* __restrict__ outFlat)
{
    extern __shared__ __align__(16) char smem_raw[];
    GemmSmem* sm = (GemmSmem*)smem_raw;

    const __half* Aeff = (mode == 0) ? g_qr : (mode == 1) ? g_kr
                       : (mode == 2) ? g_vr : g_att;
    const __half* Wt = g_wr + (long long)mode * E * E;

    const int bm = blockIdx.y * 128;
    const int bn = blockIdx.x * 128;
    const int tid  = threadIdx.x;
    const int warp = tid >> 5;
    const int lane = tid & 31;
    const int warpM = warp >> 2;
    const int warpN = warp & 3;

    const unsigned smA = (unsigned)__cvta_generic_to_shared(&sm->A[0][0][0]);
    const unsigned smB = (unsigned)__cvta_generic_to_shared(&sm->Bm[0][0][0]);
    const unsigned bufBytes = 128 * HLD * 2;

    auto issue = [&](int s, int buf) {
        const int k0 = s * 64;
        #pragma unroll
        for (int i = tid; i < 128 * 8; i += 256) {
            const int r = i >> 3, ch = i & 7;
            const unsigned o = (unsigned)buf * bufBytes + (unsigned)(r * HLD + ch * 8) * 2;
            cp_async16(smA + o, Aeff + (size_t)(bm + r) * E + k0 + ch * 8);
            cp_async16(smB + o, Wt   + (size_t)(bn + r) * E + k0 + ch * 8);
        }
    };

    wmma::fragment<wmma::accumulator, 16, 16, 16, float> c[4][2];
    #pragma unroll
    for (int mi = 0; mi < 4; ++mi)
        #pragma unroll
        for (int ni = 0; ni < 2; ++ni)
            wmma::fill_fragment(c[mi][ni], 0.0f);

    issue(0, 0);
    cp_commit();

    for (int s = 0; s < NSTG; ++s) {
        cp_wait<0>();
        __syncthreads();
        if (s + 1 < NSTG) { issue(s + 1, (s + 1) & 1); cp_commit(); }
        const int buf = s & 1;

        #pragma unroll
        for (int kc = 0; kc < 4; ++kc) {
            wmma::fragment<wmma::matrix_a, 16, 16, 16, __half, wmma::row_major> a[4];
            wmma::fragment<wmma::matrix_b, 16, 16, 16, __half, wmma::col_major> b[2];
            #pragma unroll
            for (int mi = 0; mi < 4; ++mi)
                wmma::load_matrix_sync(a[mi], &sm->A[buf][warpM * 64 + mi * 16][kc * 16], HLD);
            #pragma unroll
            for (int ni = 0; ni < 2; ++ni)
                wmma::load_matrix_sync(b[ni], &sm->Bm[buf][warpN * 32 + ni * 16][kc * 16], HLD);
            #pragma unroll
            for (int mi = 0; mi < 4; ++mi)
                #pragma unroll
                for (int ni = 0; ni < 2; ++ni)
                    wmma::mma_sync(c[mi][ni], a[mi], b[ni], c[mi][ni]);
        }
        __syncthreads();
    }

    __half* outHeads = (mode == 0) ? g_qh : (mode == 1) ? g_kh : g_vh;

    #pragma unroll
    for (int mi = 0; mi < 4; ++mi) {
        #pragma unroll
        for (int ni = 0; ni < 2; ++ni) {
            wmma::store_matrix_sync(&sm->scr[warp][0], c[mi][ni], 20, wmma::mem_row_major);
            __syncwarp();
            const int m0 = bm + warpM * 64 + mi * 16;
            const int n0 = bn + warpN * 32 + ni * 16;
            #pragma unroll
            for (int it = 0; it < 8; ++it) {
                const int idx = lane + it * 32;
                const int r = idx >> 4, cc = idx & 15;
                const int m = m0 + r;
                const int n = n0 + cc;
                const float v = (sm->scr[warp][r * 20 + cc] + bias[n]) * scale;
                if (mode == 3) {
                    outFlat[(size_t)m * E + n] = v;
                } else {
                    const int b_ = m >> 11, s_ = m & (S - 1);
                    const int h_ = n >> 6,  d_ = n & 63;
                    outHeads[(((size_t)(b_ * H + h_)) * S + s_) * DH + d_] = __float2half_rn(v);
                }
            }
            __syncwarp();
        }
    }
}

// ---------------------------------------------------------------------------
// Fused attention (fp16 MMA operands, fp32 accum/softmax):
//  per k-tile: S=QK^T, p~=exp(S-8) -> fp32 gmem probs + fp16 smem for PV,
//  l += rowsum. Epilogue: in-place probs *= 1/l, O *= 1/l.
//  K/V double-buffered cp.async, issue-ahead; 3 syncs per iteration.
// ---------------------------------------------------------------------------
struct AttnSmem {
    __half Q[BQ][HLD];      // 9216 B
    __half K[2][BK][HLD];   // 18432 B
    __half V[2][BK][HLD];   // 18432 B
    float  P[BQ][PLD];      // 17408 B
    __half Ph[BQ][HLD];     // 9216 B
    float l[BQ];
    float invl[BQ];
};

__global__ void __launch_bounds__(256, 3)
attn_fused_kernel(float* __restrict__ outw, int use_fb)
{
    extern __shared__ __align__(16) char smem_raw[];
    AttnSmem* sm = (AttnSmem*)smem_raw;

    float* wts = use_fb ? g_wfallback : outw;

    const int q0 = blockIdx.x * BQ;
    const int bh = blockIdx.y;
    const __half* Qg = g_qh + (size_t)bh * S * DH;
    const __half* Kg = g_kh + (size_t)bh * S * DH;
    const __half* Vg = g_vh + (size_t)bh * S * DH;
    float* Wb = wts + (size_t)bh * S * S;

    const int tid  = threadIdx.x;
    const int warp = tid >> 5;
    const int warpM = warp >> 1;      // 0..3 -> 16-row slice
    const int warpN = warp & 1;       // 0..1 -> 32-col slice
    const int grp  = tid >> 4;        // 0..15
    const int gln  = tid & 15;

    const unsigned smQ  = (unsigned)__cvta_generic_to_shared(&sm->Q[0][0]);
    const unsigned smK0 = (unsigned)__cvta_generic_to_shared(&sm->K[0][0][0]);
    const unsigned smV0 = (unsigned)__cvta_generic_to_shared(&sm->V[0][0][0]);
    const unsigned kBuf = BK * HLD * 2;

    // stage Q + K/V tile 0
    #pragma unroll
    for (int i = tid; i < BQ * 8; i += 256) {
        const int r = i >> 3, ch = i & 7;
        cp_async16(smQ + (unsigned)(r * HLD + ch * 8) * 2,
                   Qg + (size_t)(q0 + r) * DH + ch * 8);
    }
    #pragma unroll
    for (int i = tid; i < BK * 8; i += 256) {
        const int r = i >> 3, ch = i & 7;
        const unsigned o = (unsigned)(r * HLD + ch * 8) * 2;
        cp_async16(smK0 + o, Kg + (size_t)r * DH + ch * 8);
        cp_async16(smV0 + o, Vg + (size_t)r * DH + ch * 8);
    }
    cp_commit();
    if (tid < BQ) sm->l[tid] = 0.0f;

    wmma::fragment<wmma::accumulator, 16, 16, 16, float> o[2];
    wmma::fill_fragment(o[0], 0.0f);
    wmma::fill_fragment(o[1], 0.0f);

    for (int t = 0; t < NKT; ++t) {
        cp_wait<0>();
        __syncthreads();                 // buf t ready; prior iter's P reads done
        const int buf = t & 1;
        if (t + 1 < NKT) {               // issue-ahead into the other buffer
            const unsigned dK = smK0 + (unsigned)((t + 1) & 1) * kBuf;
            const unsigned dV = smV0 + (unsigned)((t + 1) & 1) * kBuf;
            #pragma unroll
            for (int i = tid; i < BK * 8; i += 256) {
                const int r = i >> 3, ch = i & 7;
                const unsigned off = (unsigned)(r * HLD + ch * 8) * 2;
                cp_async16(dK + off, Kg + (size_t)((t + 1) * BK + r) * DH + ch * 8);
                cp_async16(dV + off, Vg + (size_t)((t + 1) * BK + r) * DH + ch * 8);
            }
            cp_commit();
        }

        // QK: warp tile 16x32
        {
            wmma::fragment<wmma::accumulator, 16, 16, 16, float> c[2];
            wmma::fill_fragment(c[0], 0.0f);
            wmma::fill_fragment(c[1], 0.0f);
            #pragma unroll
            for (int kc = 0; kc < 4; ++kc) {
                wmma::fragment<wmma::matrix_a, 16, 16, 16, __half, wmma::row_major> a;
                wmma::load_matrix_sync(a, &sm->Q[warpM * 16][kc * 16], HLD);
                #pragma unroll
                for (int ni = 0; ni < 2; ++ni) {
                    wmma::fragment<wmma::matrix_b, 16, 16, 16, __half, wmma::col_major> b;
                    wmma::load_matrix_sync(b, &sm->K[buf][warpN * 32 + ni * 16][kc * 16], HLD);
                    wmma::mma_sync(c[ni], a, b, c[ni]);
                }
            }
            #pragma unroll
            for (int ni = 0; ni < 2; ++ni)
                wmma::store_matrix_sync(&sm->P[warpM * 16][warpN * 32 + ni * 16],
                                        c[ni], PLD, wmma::mem_row_major);
        }
        __syncthreads();

        // exp(x-8) + fp32 gmem write + fp16 round for PV + rowsum
        {
            float rs[4];
            #pragma unroll
            for (int rb = 0; rb < 4; ++rb) {
                const int r = grp + rb * 16;
                float4 x = *(float4*)&sm->P[r][gln * 4];
                x.x = __expf(fminf(x.x - EXP_OFF, 11.f));
                x.y = __expf(fminf(x.y - EXP_OFF, 11.f));
                x.z = __expf(fminf(x.z - EXP_OFF, 11.f));
                x.w = __expf(fminf(x.w - EXP_OFF, 11.f));
                *(float4*)&Wb[(size_t)(q0 + r) * S + t * BK + gln * 4] = x;
                rs[rb] = x.x + x.y + x.z + x.w;
                *(__half2*)&sm->Ph[r][gln * 4]     = __floats2half2_rn(x.x, x.y);
                *(__half2*)&sm->Ph[r][gln * 4 + 2] = __floats2half2_rn(x.z, x.w);
            }
            #pragma unroll
            for (int o_ = 8; o_; o_ >>= 1)
                #pragma unroll
                for (int rb = 0; rb < 4; ++rb)
                    rs[rb] += __shfl_xor_sync(0xffffffffu, rs[rb], o_);
            if (gln == 0)
                #pragma unroll
                for (int rb = 0; rb < 4; ++rb)
                    sm->l[grp + rb * 16] += rs[rb];
        }
        __syncthreads();

        // PV: o += Ph(64x64) @ V(64x64), warp tile 16x32
        #pragma unroll
        for (int kc = 0; kc < 4; ++kc) {
            wmma::fragment<wmma::matrix_a, 16, 16, 16, __half, wmma::row_major> a;
            wmma::load_matrix_sync(a, &sm->Ph[warpM * 16][kc * 16], HLD);
            #pragma unroll
            for (int ni = 0; ni < 2; ++ni) {
                wmma::fragment<wmma::matrix_b, 16, 16, 16, __half, wmma::row_major> b;
                wmma::load_matrix_sync(b, &sm->V[buf][kc * 16][warpN * 32 + ni * 16], HLD);
                wmma::mma_sync(o[ni], a, b, o[ni]);
            }
        }
        // top-of-loop sync guards P/Ph reuse
    }
    __syncthreads();

    if (tid < BQ) sm->invl[tid] = 1.0f / sm->l[tid];
    __syncthreads();

    // fixup: normalize this tile's probs strip in place
    for (int i = tid; i < BQ * (S / 4); i += 256) {
        const int r = i >> 9, c4 = i & 511;
        const float sc = sm->invl[r];
        float* p = &Wb[(size_t)(q0 + r) * S + c4 * 4];
        float4 x = *(float4*)p;
        x.x *= sc; x.y *= sc; x.z *= sc; x.w *= sc;
        *(float4*)p = x;
    }

    // O: frags -> P smem -> scaled fp16 scatter to g_att
    #pragma unroll
    for (int ni = 0; ni < 2; ++ni)
        wmma::store_matrix_sync(&sm->P[warpM * 16][warpN * 32 + ni * 16],
                                o[ni], PLD, wmma::mem_row_major);
    __syncthreads();

    const int b_ = bh >> 4, h_ = bh & 15;
    for (int i = tid; i < BQ * 16; i += 256) {
        const int r = i >> 4, c4 = i & 15;
        const float sc = sm->invl[r];
        float4 x = *(float4*)&sm->P[r][c4 * 4];
        __half2 h01 = __floats2half2_rn(x.x * sc, x.y * sc);
        __half2 h23 = __floats2half2_rn(x.z * sc, x.w * sc);
        __half* dst = &g_att[((size_t)(b_ * S + q0 + r)) * E + h_ * DH + c4 * 4];
        *(__half2*)dst = h01;
        *(__half2*)(dst + 2) = h23;
    }
}

// ---------------------------------------------------------------------------
extern "C" void kernel_launch(void* const* d_in, const int* in_sizes, int n_in,
                              void* d_out, int out_size)
{
    const float* q  = (const float*)d_in[0];
    const float* k  = (const float*)d_in[1];
    const float* v  = (const float*)d_in[2];
    const float* Wq = (const float*)d_in[3];
    const float* bq = (const float*)d_in[4];
    const float* Wk = (const float*)d_in[5];
    const float* bk = (const float*)d_in[6];
    const float* Wv = (const float*)d_in[7];
    const float* bv = (const float*)d_in[8];
    const float* Wo = (const float*)d_in[9];
    const float* bo = (const float*)d_in[10];
    float* out = (float*)d_out;

    const int use_fb = ((long long)out_size < OUT_ELEMS + W_ELEMS) ? 1 : 0;
    float* outw = out + OUT_ELEMS;

    static int smem_set = 0;
    const int attn_smem = (int)sizeof(AttnSmem);
    const int gemm_smem = (int)sizeof(GemmSmem);
    if (!smem_set) {
        cudaFuncSetAttribute(attn_fused_kernel,
                             cudaFuncAttributeMaxDynamicSharedMemorySize, attn_smem);
        cudaFuncSetAttribute(gemm_fp16_kernel,
                             cudaFuncAttributeMaxDynamicSharedMemorySize, gemm_smem);
        smem_set = 1;
    }

    const dim3 blk(256);
    const dim3 gemm_grid(E / 128, M / 128);   // (8, 32)

    preround_kernel<<<1024, blk>>>(q, k, v, Wq, Wk, Wv, Wo);

    gemm_fp16_kernel<<<gemm_grid, blk, gemm_smem>>>(bq, ATTN_SCALE, 0, nullptr);
    gemm_fp16_kernel<<<gemm_grid, blk, gemm_smem>>>(bk, 1.0f,       1, nullptr);
    gemm_fp16_kernel<<<gemm_grid, blk, gemm_smem>>>(bv, 1.0f,       2, nullptr);

    attn_fused_kernel<<<dim3(S / BQ, BH), blk, attn_smem>>>(outw, use_fb);

    gemm_fp16_kernel<<<gemm_grid, blk, gemm_smem>>>(bo, 1.0f, 3, out);
}

// round 9
// speedup vs baseline: 2.8627x; 1.0477x over previous
#include <cuda_runtime.h>
#include <cstdint>
#include <cuda_fp16.h>
#include <mma.h>

using namespace nvcuda;

namespace {
constexpr int B  = 2;
constexpr int S  = 2048;
constexpr int E  = 1024;
constexpr int H  = 16;
constexpr int DH = 64;
constexpr int M  = B * S;    // 4096
constexpr int BH = B * H;    // 32
constexpr long long OUT_ELEMS = (long long)B * S * E;
constexpr long long W_ELEMS   = (long long)B * H * S * S;
constexpr float ATTN_SCALE = 0.125f;

constexpr int BQ  = 64;      // q rows per tile
constexpr int BK  = 64;      // k cols per tile
constexpr int NKT = S / BK;  // 32
constexpr int HLD = 72;      // fp16 smem stride (64 + 8)
constexpr int PLD = 68;      // fp32 P stride
constexpr int NSTG = E / 64; // 16 gemm k-stages
constexpr float EXP_OFF = 8.0f;   // logit shift (cancels in softmax)
}

// Scratch (__device__ globals)
__device__ __half g_qr[(long long)M * E];
__device__ __half g_kr[(long long)M * E];
__device__ __half g_vr[(long long)M * E];
__device__ __half g_wr[4ll * E * E];
__device__ __half g_qh[(long long)BH * S * DH];
__device__ __half g_kh[(long long)BH * S * DH];
__device__ __half g_vh[(long long)BH * S * DH];
__device__ __half g_att[(long long)M * E];
__device__ __half g_ps[(long long)BH * S * S];   // unnormalized probs, fp16
__device__ float  g_wfallback[W_ELEMS];

__device__ __forceinline__ void cp_async16(unsigned dst, const void* src) {
    asm volatile("cp.async.cg.shared.global [%0], [%1], 16;\n" :: "r"(dst), "l"(src));
}
__device__ __forceinline__ void cp_commit() {
    asm volatile("cp.async.commit_group;\n" ::: "memory");
}
template <int N>
__device__ __forceinline__ void cp_wait() {
    asm volatile("cp.async.wait_group %0;\n" :: "n"(N) : "memory");
}

// ---------------------------------------------------------------------------
// Pre-round: convert q,k,v and the 4 weight matrices to fp16 scratch.
// ---------------------------------------------------------------------------
__global__ void __launch_bounds__(256)
preround_kernel(const float* __restrict__ q, const float* __restrict__ k,
                const float* __restrict__ v,
                const float* __restrict__ Wq, const float* __restrict__ Wk,
                const float* __restrict__ Wv, const float* __restrict__ Wo)
{
    const long long n4_x = (long long)M * E / 4;
    const long long n4_w = (long long)E * E / 4;
    const long long total = 3 * n4_x + 4 * n4_w;

    for (long long idx = (long long)blockIdx.x * blockDim.x + threadIdx.x;
         idx < total; idx += (long long)gridDim.x * blockDim.x) {
        const float4* src; __half2* dst; long long off;
        if (idx < n4_x)          { src = (const float4*)q; dst = (__half2*)g_qr; off = idx; }
        else if (idx < 2 * n4_x) { src = (const float4*)k; dst = (__half2*)g_kr; off = idx - n4_x; }
        else if (idx < 3 * n4_x) { src = (const float4*)v; dst = (__half2*)g_vr; off = idx - 2 * n4_x; }
        else {
            long long w = idx - 3 * n4_x;
            int wi = (int)(w / n4_w);
            off = w - (long long)wi * n4_w;
            src = (const float4*)((wi == 0) ? Wq : (wi == 1) ? Wk : (wi == 2) ? Wv : Wo);
            dst = (__half2*)(g_wr + (long long)wi * E * E);
        }
        float4 t = src[off];
        dst[off * 2]     = __floats2half2_rn(t.x, t.y);
        dst[off * 2 + 1] = __floats2half2_rn(t.z, t.w);
    }
}

// ---------------------------------------------------------------------------
// Projection GEMM (fp16 operands, fp32 accumulate), 2-stage cp.async ring.
// mode_base = -1: mode = blockIdx.z (fused q/k/v projections).
// mode_base = 3: out-projection, flat fp32 output.
// ---------------------------------------------------------------------------
struct GemmSmem {
    __half A[2][128][HLD];    // 36864 B
    __half Bm[2][128][HLD];   // 36864 B
    float scr[8][16 * 20];    // 10240 B
};

__global__ void __launch_bounds__(256, 2)
gemm_fp16_kernel(const float* __restrict__ b0, const float* __restrict__ b1,
                 const float* __restrict__ b2, int mode_base,
                 float* __restrict__ outFlat)
{
    extern __shared__ __align__(16) char smem_raw[];
    GemmSmem* sm = (GemmSmem*)smem_raw;

    const int mode = (mode_base < 0) ? (int)blockIdx.z : mode_base;
    const float* bias = (mode == 0) ? b0 : (mode == 1) ? b1 : (mode == 2) ? b2 : b0;
    const float scale = (mode == 0) ? ATTN_SCALE : 1.0f;

    const __half* Aeff = (mode == 0) ? g_qr : (mode == 1) ? g_kr
                       : (mode == 2) ? g_vr : g_att;
    const __half* Wt = g_wr + (long long)mode * E * E;

    const int bm = blockIdx.y * 128;
    const int bn = blockIdx.x * 128;
    const int tid  = threadIdx.x;
    const int warp = tid >> 5;
    const int lane = tid & 31;
    const int warpM = warp >> 2;
    const int warpN = warp & 3;

    const unsigned smA = (unsigned)__cvta_generic_to_shared(&sm->A[0][0][0]);
    const unsigned smB = (unsigned)__cvta_generic_to_shared(&sm->Bm[0][0][0]);
    const unsigned bufBytes = 128 * HLD * 2;

    auto issue = [&](int s, int buf) {
        const int k0 = s * 64;
        #pragma unroll
        for (int i = tid; i < 128 * 8; i += 256) {
            const int r = i >> 3, ch = i & 7;
            const unsigned o = (unsigned)buf * bufBytes + (unsigned)(r * HLD + ch * 8) * 2;
            cp_async16(smA + o, Aeff + (size_t)(bm + r) * E + k0 + ch * 8);
            cp_async16(smB + o, Wt   + (size_t)(bn + r) * E + k0 + ch * 8);
        }
    };

    wmma::fragment<wmma::accumulator, 16, 16, 16, float> c[4][2];
    #pragma unroll
    for (int mi = 0; mi < 4; ++mi)
        #pragma unroll
        for (int ni = 0; ni < 2; ++ni)
            wmma::fill_fragment(c[mi][ni], 0.0f);

    issue(0, 0);
    cp_commit();

    for (int s = 0; s < NSTG; ++s) {
        cp_wait<0>();
        __syncthreads();
        if (s + 1 < NSTG) { issue(s + 1, (s + 1) & 1); cp_commit(); }
        const int buf = s & 1;

        #pragma unroll
        for (int kc = 0; kc < 4; ++kc) {
            wmma::fragment<wmma::matrix_a, 16, 16, 16, __half, wmma::row_major> a[4];
            wmma::fragment<wmma::matrix_b, 16, 16, 16, __half, wmma::col_major> b[2];
            #pragma unroll
            for (int mi = 0; mi < 4; ++mi)
                wmma::load_matrix_sync(a[mi], &sm->A[buf][warpM * 64 + mi * 16][kc * 16], HLD);
            #pragma unroll
            for (int ni = 0; ni < 2; ++ni)
                wmma::load_matrix_sync(b[ni], &sm->Bm[buf][warpN * 32 + ni * 16][kc * 16], HLD);
            #pragma unroll
            for (int mi = 0; mi < 4; ++mi)
                #pragma unroll
                for (int ni = 0; ni < 2; ++ni)
                    wmma::mma_sync(c[mi][ni], a[mi], b[ni], c[mi][ni]);
        }
        __syncthreads();
    }

    __half* outHeads = (mode == 0) ? g_qh : (mode == 1) ? g_kh : g_vh;

    #pragma unroll
    for (int mi = 0; mi < 4; ++mi) {
        #pragma unroll
        for (int ni = 0; ni < 2; ++ni) {
            wmma::store_matrix_sync(&sm->scr[warp][0], c[mi][ni], 20, wmma::mem_row_major);
            __syncwarp();
            const int m0 = bm + warpM * 64 + mi * 16;
            const int n0 = bn + warpN * 32 + ni * 16;
            #pragma unroll
            for (int it = 0; it < 8; ++it) {
                const int idx = lane + it * 32;
                const int r = idx >> 4, cc = idx & 15;
                const int m = m0 + r;
                const int n = n0 + cc;
                const float v = (sm->scr[warp][r * 20 + cc] + bias[n]) * scale;
                if (mode == 3) {
                    outFlat[(size_t)m * E + n] = v;
                } else {
                    const int b_ = m >> 11, s_ = m & (S - 1);
                    const int h_ = n >> 6,  d_ = n & 63;
                    outHeads[(((size_t)(b_ * H + h_)) * S + s_) * DH + d_] = __float2half_rn(v);
                }
            }
            __syncwarp();
        }
    }
}

// ---------------------------------------------------------------------------
// Fused attention (fp16 MMA operands, fp32 accum/softmax):
//  per k-tile: S=QK^T, p~=exp(S-8) -> fp16 scratch g_ps + fp16 smem for PV,
//  l += rowsum. Epilogue: probs_out = p~ * (1/l) (fp32, written once),
//  O *= 1/l. K/V double-buffered cp.async issue-ahead.
// ---------------------------------------------------------------------------
struct AttnSmem {
    __half Q[BQ][HLD];      // 9216 B
    __half K[2][BK][HLD];   // 18432 B
    __half V[2][BK][HLD];   // 18432 B
    float  P[BQ][PLD];      // 17408 B
    __half Ph[BQ][HLD];     // 9216 B
    float l[BQ];
    float invl[BQ];
};

__global__ void __launch_bounds__(256, 3)
attn_fused_kernel(float* __restrict__ outw, int use_fb)
{
    extern __shared__ __align__(16) char smem_raw[];
    AttnSmem* sm = (AttnSmem*)smem_raw;

    float* wts = use_fb ? g_wfallback : outw;

    const int q0 = blockIdx.x * BQ;
    const int bh = blockIdx.y;
    const __half* Qg = g_qh + (size_t)bh * S * DH;
    const __half* Kg = g_kh + (size_t)bh * S * DH;
    const __half* Vg = g_vh + (size_t)bh * S * DH;
    float* Wb = wts + (size_t)bh * S * S;
    __half* Pg = g_ps + (size_t)bh * S * S;

    const int tid  = threadIdx.x;
    const int warp = tid >> 5;
    const int warpM = warp >> 1;      // 0..3 -> 16-row slice
    const int warpN = warp & 1;       // 0..1 -> 32-col slice
    const int grp  = tid >> 4;        // 0..15
    const int gln  = tid & 15;

    const unsigned smQ  = (unsigned)__cvta_generic_to_shared(&sm->Q[0][0]);
    const unsigned smK0 = (unsigned)__cvta_generic_to_shared(&sm->K[0][0][0]);
    const unsigned smV0 = (unsigned)__cvta_generic_to_shared(&sm->V[0][0][0]);
    const unsigned kBuf = BK * HLD * 2;

    // stage Q + K/V tile 0
    #pragma unroll
    for (int i = tid; i < BQ * 8; i += 256) {
        const int r = i >> 3, ch = i & 7;
        cp_async16(smQ + (unsigned)(r * HLD + ch * 8) * 2,
                   Qg + (size_t)(q0 + r) * DH + ch * 8);
    }
    #pragma unroll
    for (int i = tid; i < BK * 8; i += 256) {
        const int r = i >> 3, ch = i & 7;
        const unsigned o = (unsigned)(r * HLD + ch * 8) * 2;
        cp_async16(smK0 + o, Kg + (size_t)r * DH + ch * 8);
        cp_async16(smV0 + o, Vg + (size_t)r * DH + ch * 8);
    }
    cp_commit();
    if (tid < BQ) sm->l[tid] = 0.0f;

    wmma::fragment<wmma::accumulator, 16, 16, 16, float> o[2];
    wmma::fill_fragment(o[0], 0.0f);
    wmma::fill_fragment(o[1], 0.0f);

    for (int t = 0; t < NKT; ++t) {
        cp_wait<0>();
        __syncthreads();                 // buf t ready; prior iter's P reads done
        const int buf = t & 1;
        if (t + 1 < NKT) {               // issue-ahead into the other buffer
            const unsigned dK = smK0 + (unsigned)((t + 1) & 1) * kBuf;
            const unsigned dV = smV0 + (unsigned)((t + 1) & 1) * kBuf;
            #pragma unroll
            for (int i = tid; i < BK * 8; i += 256) {
                const int r = i >> 3, ch = i & 7;
                const unsigned off = (unsigned)(r * HLD + ch * 8) * 2;
                cp_async16(dK + off, Kg + (size_t)((t + 1) * BK + r) * DH + ch * 8);
                cp_async16(dV + off, Vg + (size_t)((t + 1) * BK + r) * DH + ch * 8);
            }
            cp_commit();
        }

        // QK: warp tile 16x32
        {
            wmma::fragment<wmma::accumulator, 16, 16, 16, float> c[2];
            wmma::fill_fragment(c[0], 0.0f);
            wmma::fill_fragment(c[1], 0.0f);
            #pragma unroll
            for (int kc = 0; kc < 4; ++kc) {
                wmma::fragment<wmma::matrix_a, 16, 16, 16, __half, wmma::row_major> a;
                wmma::load_matrix_sync(a, &sm->Q[warpM * 16][kc * 16], HLD);
                #pragma unroll
                for (int ni = 0; ni < 2; ++ni) {
                    wmma::fragment<wmma::matrix_b, 16, 16, 16, __half, wmma::col_major> b;
                    wmma::load_matrix_sync(b, &sm->K[buf][warpN * 32 + ni * 16][kc * 16], HLD);
                    wmma::mma_sync(c[ni], a, b, c[ni]);
                }
            }
            #pragma unroll
            for (int ni = 0; ni < 2; ++ni)
                wmma::store_matrix_sync(&sm->P[warpM * 16][warpN * 32 + ni * 16],
                                        c[ni], PLD, wmma::mem_row_major);
        }
        __syncthreads();

        // exp(x-8) -> fp16: scratch gmem write (8B) + smem Ph for PV + rowsum
        {
            float rs[4];
            #pragma unroll
            for (int rb = 0; rb < 4; ++rb) {
                const int r = grp + rb * 16;
                float4 x = *(float4*)&sm->P[r][gln * 4];
                x.x = __expf(fminf(x.x - EXP_OFF, 11.f));
                x.y = __expf(fminf(x.y - EXP_OFF, 11.f));
                x.z = __expf(fminf(x.z - EXP_OFF, 11.f));
                x.w = __expf(fminf(x.w - EXP_OFF, 11.f));
                rs[rb] = x.x + x.y + x.z + x.w;
                union { __half2 h2[2]; uint2 u; } pk;
                pk.h2[0] = __floats2half2_rn(x.x, x.y);
                pk.h2[1] = __floats2half2_rn(x.z, x.w);
                *(uint2*)&Pg[(size_t)(q0 + r) * S + t * BK + gln * 4] = pk.u;
                *(uint2*)&sm->Ph[r][gln * 4] = pk.u;
            }
            #pragma unroll
            for (int o_ = 8; o_; o_ >>= 1)
                #pragma unroll
                for (int rb = 0; rb < 4; ++rb)
                    rs[rb] += __shfl_xor_sync(0xffffffffu, rs[rb], o_);
            if (gln == 0)
                #pragma unroll
                for (int rb = 0; rb < 4; ++rb)
                    sm->l[grp + rb * 16] += rs[rb];
        }
        __syncthreads();

        // PV: o += Ph(64x64) @ V(64x64), warp tile 16x32
        #pragma unroll
        for (int kc = 0; kc < 4; ++kc) {
            wmma::fragment<wmma::matrix_a, 16, 16, 16, __half, wmma::row_major> a;
            wmma::load_matrix_sync(a, &sm->Ph[warpM * 16][kc * 16], HLD);
            #pragma unroll
            for (int ni = 0; ni < 2; ++ni) {
                wmma::fragment<wmma::matrix_b, 16, 16, 16, __half, wmma::row_major> b;
                wmma::load_matrix_sync(b, &sm->V[buf][kc * 16][warpN * 32 + ni * 16], HLD);
                wmma::mma_sync(o[ni], a, b, o[ni]);
            }
        }
        // top-of-loop sync guards P/Ph reuse
    }
    __syncthreads();

    if (tid < BQ) sm->invl[tid] = 1.0f / sm->l[tid];
    __syncthreads();

    // normalize: read fp16 p~ strip (L2-resident), write fp32 probs once
    for (int i = tid; i < BQ * (S / 4); i += 256) {
        const int r = i >> 9, c4 = i & 511;
        const float sc = sm->invl[r];
        union { uint2 u; __half2 h2[2]; } pk;
        pk.u = *(const uint2*)&Pg[(size_t)(q0 + r) * S + c4 * 4];
        const float2 a = __half22float2(pk.h2[0]);
        const float2 b = __half22float2(pk.h2[1]);
        float4 x;
        x.x = a.x * sc; x.y = a.y * sc; x.z = b.x * sc; x.w = b.y * sc;
        *(float4*)&Wb[(size_t)(q0 + r) * S + c4 * 4] = x;
    }

    // O: frags -> P smem -> scaled fp16 scatter to g_att
    #pragma unroll
    for (int ni = 0; ni < 2; ++ni)
        wmma::store_matrix_sync(&sm->P[warpM * 16][warpN * 32 + ni * 16],
                                o[ni], PLD, wmma::mem_row_major);
    __syncthreads();

    const int b_ = bh >> 4, h_ = bh & 15;
    for (int i = tid; i < BQ * 16; i += 256) {
        const int r = i >> 4, c4 = i & 15;
        const float sc = sm->invl[r];
        float4 x = *(float4*)&sm->P[r][c4 * 4];
        __half2 h01 = __floats2half2_rn(x.x * sc, x.y * sc);
        __half2 h23 = __floats2half2_rn(x.z * sc, x.w * sc);
        __half* dst = &g_att[((size_t)(b_ * S + q0 + r)) * E + h_ * DH + c4 * 4];
        *(__half2*)dst = h01;
        *(__half2*)(dst + 2) = h23;
    }
}

// ---------------------------------------------------------------------------
extern "C" void kernel_launch(void* const* d_in, const int* in_sizes, int n_in,
                              void* d_out, int out_size)
{
    const float* q  = (const float*)d_in[0];
    const float* k  = (const float*)d_in[1];
    const float* v  = (const float*)d_in[2];
    const float* Wq = (const float*)d_in[3];
    const float* bq = (const float*)d_in[4];
    const float* Wk = (const float*)d_in[5];
    const float* bk = (const float*)d_in[6];
    const float* Wv = (const float*)d_in[7];
    const float* bv = (const float*)d_in[8];
    const float* Wo = (const float*)d_in[9];
    const float* bo = (const float*)d_in[10];
    float* out = (float*)d_out;

    const int use_fb = ((long long)out_size < OUT_ELEMS + W_ELEMS) ? 1 : 0;
    float* outw = out + OUT_ELEMS;

    static int smem_set = 0;
    const int attn_smem = (int)sizeof(AttnSmem);
    const int gemm_smem = (int)sizeof(GemmSmem);
    if (!smem_set) {
        cudaFuncSetAttribute(attn_fused_kernel,
                             cudaFuncAttributeMaxDynamicSharedMemorySize, attn_smem);
        cudaFuncSetAttribute(gemm_fp16_kernel,
                             cudaFuncAttributeMaxDynamicSharedMemorySize, gemm_smem);
        smem_set = 1;
    }

    const dim3 blk(256);

    preround_kernel<<<1024, blk>>>(q, k, v, Wq, Wk, Wv, Wo);

    // fused q/k/v projections: blockIdx.z selects mode
    gemm_fp16_kernel<<<dim3(E / 128, M / 128, 3), blk, gemm_smem>>>(bq, bk, bv, -1, nullptr);

    attn_fused_kernel<<<dim3(S / BQ, BH), blk, attn_smem>>>(outw, use_fb);

    gemm_fp16_kernel<<<dim3(E / 128, M / 128, 1), blk, gemm_smem>>>(bo, bo, bo, 3, out);
}